// round 15
// baseline (speedup 1.0000x reference)
#include <cuda_runtime.h>
#include <cuda_bf16.h>
#include <cstdint>

#define B_  2
#define S_  2048
#define D_  1024
#define H_  16
#define HD_ 64
#define M_  (B_*S_)   // 4096

// ---------------------------------------------------------------------------
// Scratch (device globals). All split bf16 pairs.
// ---------------------------------------------------------------------------
__device__ __nv_bfloat16 g_decH[M_*D_], g_decL[M_*D_];
__device__ __nv_bfloat16 g_encH[M_*D_], g_encL[M_*D_];
__device__ __nv_bfloat16 g_qH[M_*D_],   g_qL[M_*D_];
__device__ __nv_bfloat16 g_kH[M_*D_],   g_kL[M_*D_];
__device__ __nv_bfloat16 g_vH[M_*D_],   g_vL[M_*D_];
__device__ __nv_bfloat16 g_yH[M_*D_],   g_yL[M_*D_];
__device__ __nv_bfloat16 g_wqH[D_*D_],  g_wqL[D_*D_];
__device__ __nv_bfloat16 g_wkH[D_*D_],  g_wkL[D_*D_];
__device__ __nv_bfloat16 g_wvH[D_*D_],  g_wvL[D_*D_];
__device__ __nv_bfloat16 g_wpH[D_*D_],  g_wpL[D_*D_];

// ---------------------------------------------------------------------------
// fp32 -> (hi, lo) bf16 splits
// ---------------------------------------------------------------------------
__device__ __forceinline__ void split4_store(const float4 v,
                                             __nv_bfloat16* hi, __nv_bfloat16* lo, int i)
{
    float x[4] = {v.x, v.y, v.z, v.w};
    unsigned short h[4], l[4];
#pragma unroll
    for (int j = 0; j < 4; j++) {
        __nv_bfloat16 hb = __float2bfloat16(x[j]);
        __nv_bfloat16 lb = __float2bfloat16(x[j] - __bfloat162float(hb));
        h[j] = __bfloat16_as_ushort(hb);
        l[j] = __bfloat16_as_ushort(lb);
    }
    uint2 hv, lv;
    hv.x = (uint32_t)h[0] | ((uint32_t)h[1] << 16);
    hv.y = (uint32_t)h[2] | ((uint32_t)h[3] << 16);
    lv.x = (uint32_t)l[0] | ((uint32_t)l[1] << 16);
    lv.y = (uint32_t)l[2] | ((uint32_t)l[3] << 16);
    ((uint2*)hi)[i] = hv;
    ((uint2*)lo)[i] = lv;
}

#define NACT4_ (M_*D_/4)
__global__ __launch_bounds__(256)
void split_act2(const float* __restrict__ A0, const float* __restrict__ A1,
                __nv_bfloat16* __restrict__ H0, __nv_bfloat16* __restrict__ L0,
                __nv_bfloat16* __restrict__ H1, __nv_bfloat16* __restrict__ L1)
{
    int i = blockIdx.x * blockDim.x + threadIdx.x;
    int which = i >> 20;
    int idx   = i & (NACT4_ - 1);
    if (which == 0) split4_store(((const float4*)A0)[idx], H0, L0, idx);
    else            split4_store(((const float4*)A1)[idx], H1, L1, idx);
}

#define NW4_ (D_*D_/4)
__global__ __launch_bounds__(256)
void split_w4(const float* __restrict__ W0, const float* __restrict__ W1,
              const float* __restrict__ W2, const float* __restrict__ W3,
              __nv_bfloat16* __restrict__ H0, __nv_bfloat16* __restrict__ L0,
              __nv_bfloat16* __restrict__ H1, __nv_bfloat16* __restrict__ L1,
              __nv_bfloat16* __restrict__ H2, __nv_bfloat16* __restrict__ L2,
              __nv_bfloat16* __restrict__ H3, __nv_bfloat16* __restrict__ L3)
{
    int i = blockIdx.x * blockDim.x + threadIdx.x;
    int which = i >> 18;
    int idx   = i & (NW4_ - 1);
    const float* src; __nv_bfloat16 *hi, *lo;
    switch (which) {
        case 0:  src = W0; hi = H0; lo = L0; break;
        case 1:  src = W1; hi = H1; lo = L1; break;
        case 2:  src = W2; hi = H2; lo = L2; break;
        default: src = W3; hi = H3; lo = L3; break;
    }
    split4_store(((const float4*)src)[idx], hi, lo, idx);
}

// ---------------------------------------------------------------------------
// Helpers (baseline PTX only)
// ---------------------------------------------------------------------------
__device__ __forceinline__ uint32_t smem_u32(const void* p) {
    uint32_t a;
    asm("{ .reg .u64 t; cvta.to.shared.u64 t, %1; cvt.u32.u64 %0, t; }"
        : "=r"(a) : "l"(p));
    return a;
}

__device__ __forceinline__ void mma16816(float* c, const uint32_t* a, const uint32_t* b) {
    asm volatile(
        "mma.sync.aligned.m16n8k16.row.col.f32.bf16.bf16.f32 "
        "{%0,%1,%2,%3}, {%4,%5,%6,%7}, {%8,%9}, {%0,%1,%2,%3};"
        : "+f"(c[0]), "+f"(c[1]), "+f"(c[2]), "+f"(c[3])
        : "r"(a[0]), "r"(a[1]), "r"(a[2]), "r"(a[3]), "r"(b[0]), "r"(b[1]));
}

__device__ __forceinline__ void ldsm4(uint32_t& r0, uint32_t& r1,
                                      uint32_t& r2, uint32_t& r3, uint32_t addr) {
    asm volatile("ldmatrix.sync.aligned.m8n8.x4.shared.b16 {%0,%1,%2,%3}, [%4];"
                 : "=r"(r0), "=r"(r1), "=r"(r2), "=r"(r3) : "r"(addr));
}
__device__ __forceinline__ void ldsm4t(uint32_t& r0, uint32_t& r1,
                                       uint32_t& r2, uint32_t& r3, uint32_t addr) {
    asm volatile("ldmatrix.sync.aligned.m8n8.x4.trans.shared.b16 {%0,%1,%2,%3}, [%4];"
                 : "=r"(r0), "=r"(r1), "=r"(r2), "=r"(r3) : "r"(addr));
}

__device__ __forceinline__ void cp_async16(uint32_t dst, const void* src) {
    asm volatile("cp.async.cg.shared.global [%0], [%1], 16;\n"
                 :: "r"(dst), "l"(src) : "memory");
}
__device__ __forceinline__ void cp_commit() {
    asm volatile("cp.async.commit_group;\n" ::: "memory");
}
__device__ __forceinline__ void cp_wait1() {
    asm volatile("cp.async.wait_group 1;\n" ::: "memory");
}
__device__ __forceinline__ void cp_wait0() {
    asm volatile("cp.async.wait_group 0;\n" ::: "memory");
}

__device__ __forceinline__ void split2(float x, float y, uint32_t& hi, uint32_t& lo) {
    __nv_bfloat16 xh = __float2bfloat16(x);
    __nv_bfloat16 yh = __float2bfloat16(y);
    __nv_bfloat16 xl = __float2bfloat16(x - __bfloat162float(xh));
    __nv_bfloat16 yl = __float2bfloat16(y - __bfloat162float(yh));
    __nv_bfloat162 hv; hv.x = xh; hv.y = yh;
    __nv_bfloat162 lv; lv.x = xl; lv.y = yl;
    hi = *(uint32_t*)&hv; lo = *(uint32_t*)&lv;
}

// ---------------------------------------------------------------------------
// bf16x3 split GEMM v3: CTA 128x128, 4 warps of 64x64.
// Register-lean loop order: hold all B frags (32 regs) per k-step, stream A
// per mi (8 regs live). acc 128 + B 32 + A 8 ~= 190 regs -> no spill.
// ---------------------------------------------------------------------------
#define KSTEP    32
#define NSTAGE   (D_ / KSTEP)
#define ROWH     40
#define ARRB     (128 * ROWH * 2)
#define STAGEB   (4 * ARRB)
#define GSMEM    (2 * STAGEB)

__global__ __launch_bounds__(128, 2)
void gemm_hmma3(const __nv_bfloat16* __restrict__ Ah, const __nv_bfloat16* __restrict__ Al,
                const __nv_bfloat16* __restrict__ Wh, const __nv_bfloat16* __restrict__ Wl,
                const float* __restrict__ bias,
                float* __restrict__ CF,
                __nv_bfloat16* __restrict__ CH, __nv_bfloat16* __restrict__ CL,
                float scale)
{
    extern __shared__ __align__(16) uint16_t sm[];

    const int tid  = threadIdx.x;
    const int wid  = tid >> 5;       // 0..3
    const int lane = tid & 31;
    const int g    = lane >> 2;
    const int t2   = (lane & 3) * 2;
    const int wm   = wid >> 1;       // 0..1
    const int wn   = wid & 1;        // 0..1
    const int bn   = blockIdx.x * 128;
    const int bm   = blockIdx.y * 128;

    const int lr   = lane & 7;
    const int lrow = lr + 8 * ((lane >> 3) & 1);   // A row sel
    const int lkh  = 8 * ((lane >> 4) & 1);        // A k sel
    const int brow = lr + 8 * ((lane >> 4) & 1);   // B row sel
    const int bk   = 8 * ((lane >> 3) & 1);        // B k sel

    const uint32_t smb = smem_u32(sm);

    auto load_stage = [&](int s) {
        const int buf = s & 1;
        const int k0  = s * KSTEP;
        const uint32_t base = smb + buf * STAGEB;
#pragma unroll
        for (int i = 0; i < 16; i++) {
            const int c   = i * 128 + tid;
            const int arr = i >> 2;              // constant per unrolled i
            const int idx = c & 511;
            const int row = idx >> 2;
            const int q   = idx & 3;
            const __nv_bfloat16* gp = (arr == 0) ? Ah : (arr == 1) ? Al
                                    : (arr == 2) ? Wh : Wl;
            const int r0 = (arr < 2) ? bm : bn;
            cp_async16(base + arr * ARRB + row * (ROWH * 2) + q * 16,
                       gp + (size_t)(r0 + row) * D_ + k0 + q * 8);
        }
        cp_commit();
    };

    float acc[4][8][4];
#pragma unroll
    for (int mi = 0; mi < 4; mi++)
#pragma unroll
        for (int nj = 0; nj < 8; nj++)
#pragma unroll
            for (int r = 0; r < 4; r++) acc[mi][nj][r] = 0.0f;

    load_stage(0);
    load_stage(1);

    for (int s = 0; s < NSTAGE; s++) {
        const int buf = s & 1;
        if (s < NSTAGE - 1) cp_wait1(); else cp_wait0();
        __syncthreads();

        const uint32_t sb = smb + buf * STAGEB;

#pragma unroll
        for (int ks = 0; ks < 2; ks++) {
            const int ko = ks * 16;

            // ---- B resident for the whole k-step: 8 ldsm4 = 32 regs ----
            uint32_t bh[4][4], bl[4][4];
            const uint32_t bB = sb + 2 * ARRB
                              + ((wn * 64 + brow) * ROWH + ko + bk) * 2;
#pragma unroll
            for (int jp = 0; jp < 4; jp++) {
                ldsm4(bh[jp][0], bh[jp][1], bh[jp][2], bh[jp][3],
                      bB + jp * (16 * ROWH * 2));
                ldsm4(bl[jp][0], bl[jp][1], bl[jp][2], bl[jp][3],
                      bB + ARRB + jp * (16 * ROWH * 2));
            }

            // ---- stream A per mi: 2 ldsm4 (8 regs) live at a time ----
            const uint32_t aA = sb + ((wm * 64 + lrow) * ROWH + ko + lkh) * 2;
#pragma unroll
            for (int mi = 0; mi < 4; mi++) {
                uint32_t ah4[4], al4[4];
                ldsm4(ah4[0], ah4[1], ah4[2], ah4[3],
                      aA + mi * (16 * ROWH * 2));
                ldsm4(al4[0], al4[1], al4[2], al4[3],
                      aA + ARRB + mi * (16 * ROWH * 2));
                // term 1: Ah * Wh
#pragma unroll
                for (int jp = 0; jp < 4; jp++) {
                    mma16816(acc[mi][2*jp],   ah4, &bh[jp][0]);
                    mma16816(acc[mi][2*jp+1], ah4, &bh[jp][2]);
                }
                // term 2: Ah * Wl
#pragma unroll
                for (int jp = 0; jp < 4; jp++) {
                    mma16816(acc[mi][2*jp],   ah4, &bl[jp][0]);
                    mma16816(acc[mi][2*jp+1], ah4, &bl[jp][2]);
                }
                // term 3: Al * Wh
#pragma unroll
                for (int jp = 0; jp < 4; jp++) {
                    mma16816(acc[mi][2*jp],   al4, &bh[jp][0]);
                    mma16816(acc[mi][2*jp+1], al4, &bh[jp][2]);
                }
            }
        }
        __syncthreads();
        if (s + 2 < NSTAGE) load_stage(s + 2);
    }

    // ---- epilogue ----
#pragma unroll
    for (int mi = 0; mi < 4; mi++) {
        const int r0 = bm + wm * 64 + mi * 16 + g;
#pragma unroll
        for (int nj = 0; nj < 8; nj++) {
            const int c0 = bn + wn * 64 + nj * 8 + t2;
            const float b0 = bias[c0], b1 = bias[c0 + 1];
            float v00 = acc[mi][nj][0] + b0, v01 = acc[mi][nj][1] + b1;
            float v10 = acc[mi][nj][2] + b0, v11 = acc[mi][nj][3] + b1;
            if (CF) {
                *(float2*)&CF[(size_t)r0 * D_ + c0]       = make_float2(v00, v01);
                *(float2*)&CF[(size_t)(r0 + 8) * D_ + c0] = make_float2(v10, v11);
            } else {
                uint32_t h0, l0, h1, l1;
                split2(v00 * scale, v01 * scale, h0, l0);
                split2(v10 * scale, v11 * scale, h1, l1);
                *(uint32_t*)&CH[(size_t)r0 * D_ + c0]       = h0;
                *(uint32_t*)&CL[(size_t)r0 * D_ + c0]       = l0;
                *(uint32_t*)&CH[(size_t)(r0 + 8) * D_ + c0] = h1;
                *(uint32_t*)&CL[(size_t)(r0 + 8) * D_ + c0] = l1;
            }
        }
    }
}

// ---------------------------------------------------------------------------
// HMMA flash-attention v2 (unchanged — validated ~269us).
// ---------------------------------------------------------------------------
#define AT_ARR   4608
#define AT_SMEM  (8 * AT_ARR * 2)
#define NTILE_   (S_ / 64)

__global__ __launch_bounds__(128, 2)
void attn_hmma(const __nv_bfloat16* __restrict__ qH, const __nv_bfloat16* __restrict__ qL,
               const __nv_bfloat16* __restrict__ kH, const __nv_bfloat16* __restrict__ kL,
               const __nv_bfloat16* __restrict__ vH, const __nv_bfloat16* __restrict__ vL,
               __nv_bfloat16* __restrict__ yH, __nv_bfloat16* __restrict__ yL)
{
    extern __shared__ __align__(16) uint16_t sm[];
    const int tid  = threadIdx.x;
    const int wid  = tid >> 5;
    const int lane = tid & 31;
    const int g    = lane >> 2;
    const int t2   = (lane & 3) * 2;
    const int q0   = blockIdx.x * 128;
    const int bh   = blockIdx.y;
    const int b    = bh >> 4;
    const int h    = bh & 15;
    const int col0 = h * HD_;
    const int m0   = b * S_ + q0 + wid * 32;

    const int krow = (lane & 7) + 8 * ((lane >> 4) & 1);
    const int kc16 = 16 * ((lane >> 3) & 1);
    const int vrow = (lane & 7) + 8 * ((lane >> 3) & 1);
    const int vc16 = 16 * ((lane >> 4) & 1);

    uint32_t qh[2][4][4], ql[2][4][4];
#pragma unroll
    for (int mi = 0; mi < 2; mi++) {
        const int r0 = m0 + mi * 16;
        const __nv_bfloat16* p0h = qH + (size_t)(r0 + g) * D_ + col0;
        const __nv_bfloat16* p1h = qH + (size_t)(r0 + g + 8) * D_ + col0;
        const __nv_bfloat16* p0l = qL + (size_t)(r0 + g) * D_ + col0;
        const __nv_bfloat16* p1l = qL + (size_t)(r0 + g + 8) * D_ + col0;
#pragma unroll
        for (int kc = 0; kc < 4; kc++) {
            qh[mi][kc][0] = *(const uint32_t*)(p0h + kc * 16 + t2);
            qh[mi][kc][1] = *(const uint32_t*)(p1h + kc * 16 + t2);
            qh[mi][kc][2] = *(const uint32_t*)(p0h + kc * 16 + t2 + 8);
            qh[mi][kc][3] = *(const uint32_t*)(p1h + kc * 16 + t2 + 8);
            ql[mi][kc][0] = *(const uint32_t*)(p0l + kc * 16 + t2);
            ql[mi][kc][1] = *(const uint32_t*)(p1l + kc * 16 + t2);
            ql[mi][kc][2] = *(const uint32_t*)(p0l + kc * 16 + t2 + 8);
            ql[mi][kc][3] = *(const uint32_t*)(p1l + kc * 16 + t2 + 8);
        }
    }

    const uint32_t smb = smem_u32(sm);
    const __nv_bfloat16* gsrc[4] = {kH, kL, vH, vL};

    auto load_tile = [&](int kb, int buf) {
#pragma unroll
        for (int i = 0; i < 16; i++) {
            int c = i * 128 + tid;
            int a = c >> 9;
            int idx = c & 511;
            int row = idx >> 3, qq = idx & 7;
            uint32_t dst = smb + ((buf * 4 + a) * AT_ARR + row * 72 + qq * 8) * 2;
            const __nv_bfloat16* src = gsrc[a]
                + (size_t)(b * S_ + kb + row) * D_ + col0 + qq * 8;
            cp_async16(dst, src);
        }
        cp_commit();
    };

    float of[2][8][4];
#pragma unroll
    for (int mi = 0; mi < 2; mi++)
#pragma unroll
        for (int j = 0; j < 8; j++)
#pragma unroll
            for (int r = 0; r < 4; r++) of[mi][j][r] = 0.0f;
    float mr[4] = {-1e30f, -1e30f, -1e30f, -1e30f};
    float lr[4] = {0.0f, 0.0f, 0.0f, 0.0f};

    load_tile(0, 0);

    for (int it = 0; it < NTILE_; it++) {
        const int buf = it & 1;
        cp_wait0();
        __syncthreads();
        if (it + 1 < NTILE_) load_tile((it + 1) * 64, buf ^ 1);

        const uint32_t Khb = smb + (buf * 4 + 0) * AT_ARR * 2;
        const uint32_t Klb = smb + (buf * 4 + 1) * AT_ARR * 2;
        const uint32_t Vhb = smb + (buf * 4 + 2) * AT_ARR * 2;
        const uint32_t Vlb = smb + (buf * 4 + 3) * AT_ARR * 2;

        float sf[2][8][4];
#pragma unroll
        for (int mi = 0; mi < 2; mi++)
#pragma unroll
            for (int j = 0; j < 8; j++)
#pragma unroll
                for (int r = 0; r < 4; r++) sf[mi][j][r] = 0.0f;

#pragma unroll
        for (int kc = 0; kc < 4; kc++) {
#pragma unroll
            for (int jp = 0; jp < 4; jp++) {
                uint32_t kh4[4], kl4[4];
                const uint32_t off = (jp * 16 + krow) * 144 + kc * 32 + kc16;
                ldsm4(kh4[0], kh4[1], kh4[2], kh4[3], Khb + off);
                ldsm4(kl4[0], kl4[1], kl4[2], kl4[3], Klb + off);
#pragma unroll
                for (int mi = 0; mi < 2; mi++) {
                    mma16816(sf[mi][2*jp],   qh[mi][kc], &kh4[0]);
                    mma16816(sf[mi][2*jp+1], qh[mi][kc], &kh4[2]);
                }
#pragma unroll
                for (int mi = 0; mi < 2; mi++) {
                    mma16816(sf[mi][2*jp],   qh[mi][kc], &kl4[0]);
                    mma16816(sf[mi][2*jp+1], qh[mi][kc], &kl4[2]);
                }
#pragma unroll
                for (int mi = 0; mi < 2; mi++) {
                    mma16816(sf[mi][2*jp],   ql[mi][kc], &kh4[0]);
                    mma16816(sf[mi][2*jp+1], ql[mi][kc], &kh4[2]);
                }
            }
        }

#pragma unroll
        for (int mi = 0; mi < 2; mi++) {
            float tm0 = -1e30f, tm1 = -1e30f;
#pragma unroll
            for (int j = 0; j < 8; j++) {
                tm0 = fmaxf(tm0, fmaxf(sf[mi][j][0], sf[mi][j][1]));
                tm1 = fmaxf(tm1, fmaxf(sf[mi][j][2], sf[mi][j][3]));
            }
            tm0 = fmaxf(tm0, __shfl_xor_sync(0xffffffffu, tm0, 1));
            tm0 = fmaxf(tm0, __shfl_xor_sync(0xffffffffu, tm0, 2));
            tm1 = fmaxf(tm1, __shfl_xor_sync(0xffffffffu, tm1, 1));
            tm1 = fmaxf(tm1, __shfl_xor_sync(0xffffffffu, tm1, 2));
            const float mn0 = fmaxf(mr[mi*2],   tm0);
            const float mn1 = fmaxf(mr[mi*2+1], tm1);
            const float al0 = __expf(mr[mi*2]   - mn0);
            const float al1 = __expf(mr[mi*2+1] - mn1);
            float rs0 = 0.0f, rs1 = 0.0f;
#pragma unroll
            for (int j = 0; j < 8; j++) {
                sf[mi][j][0] = __expf(sf[mi][j][0] - mn0);
                sf[mi][j][1] = __expf(sf[mi][j][1] - mn0);
                sf[mi][j][2] = __expf(sf[mi][j][2] - mn1);
                sf[mi][j][3] = __expf(sf[mi][j][3] - mn1);
                rs0 += sf[mi][j][0] + sf[mi][j][1];
                rs1 += sf[mi][j][2] + sf[mi][j][3];
            }
            rs0 += __shfl_xor_sync(0xffffffffu, rs0, 1);
            rs0 += __shfl_xor_sync(0xffffffffu, rs0, 2);
            rs1 += __shfl_xor_sync(0xffffffffu, rs1, 1);
            rs1 += __shfl_xor_sync(0xffffffffu, rs1, 2);
            lr[mi*2]   = lr[mi*2]   * al0 + rs0;
            lr[mi*2+1] = lr[mi*2+1] * al1 + rs1;
            mr[mi*2] = mn0; mr[mi*2+1] = mn1;
#pragma unroll
            for (int j = 0; j < 8; j++) {
                of[mi][j][0] *= al0; of[mi][j][1] *= al0;
                of[mi][j][2] *= al1; of[mi][j][3] *= al1;
            }
        }

#pragma unroll
        for (int kc = 0; kc < 4; kc++) {
            uint32_t pah[2][4], pal[2][4];
#pragma unroll
            for (int mi = 0; mi < 2; mi++) {
                split2(sf[mi][2*kc][0],   sf[mi][2*kc][1],   pah[mi][0], pal[mi][0]);
                split2(sf[mi][2*kc][2],   sf[mi][2*kc][3],   pah[mi][1], pal[mi][1]);
                split2(sf[mi][2*kc+1][0], sf[mi][2*kc+1][1], pah[mi][2], pal[mi][2]);
                split2(sf[mi][2*kc+1][2], sf[mi][2*kc+1][3], pah[mi][3], pal[mi][3]);
            }
#pragma unroll
            for (int dp = 0; dp < 4; dp++) {
                uint32_t vh4[4], vl4[4];
                const uint32_t off = (kc * 16 + vrow) * 144 + dp * 32 + vc16;
                ldsm4t(vh4[0], vh4[1], vh4[2], vh4[3], Vhb + off);
                ldsm4t(vl4[0], vl4[1], vl4[2], vl4[3], Vlb + off);
#pragma unroll
                for (int mi = 0; mi < 2; mi++) {
                    mma16816(of[mi][2*dp],   pah[mi], &vh4[0]);
                    mma16816(of[mi][2*dp+1], pah[mi], &vh4[2]);
                }
#pragma unroll
                for (int mi = 0; mi < 2; mi++) {
                    mma16816(of[mi][2*dp],   pah[mi], &vl4[0]);
                    mma16816(of[mi][2*dp+1], pah[mi], &vl4[2]);
                }
#pragma unroll
                for (int mi = 0; mi < 2; mi++) {
                    mma16816(of[mi][2*dp],   pal[mi], &vh4[0]);
                    mma16816(of[mi][2*dp+1], pal[mi], &vh4[2]);
                }
            }
        }
    }

#pragma unroll
    for (int mi = 0; mi < 2; mi++) {
        const float inv0 = 1.0f / lr[mi*2];
        const float inv1 = 1.0f / lr[mi*2+1];
        const int r0 = m0 + mi * 16;
#pragma unroll
        for (int j = 0; j < 8; j++) {
            uint32_t h0, l0, h1, l1;
            split2(of[mi][j][0] * inv0, of[mi][j][1] * inv0, h0, l0);
            split2(of[mi][j][2] * inv1, of[mi][j][3] * inv1, h1, l1);
            const size_t o0 = (size_t)(r0 + g) * D_ + col0 + j * 8 + t2;
            const size_t o1 = (size_t)(r0 + g + 8) * D_ + col0 + j * 8 + t2;
            *(uint32_t*)&yH[o0] = h0;
            *(uint32_t*)&yL[o0] = l0;
            *(uint32_t*)&yH[o1] = h1;
            *(uint32_t*)&yL[o1] = l1;
        }
    }
}

// ---------------------------------------------------------------------------
// Launch
// ---------------------------------------------------------------------------
extern "C" void kernel_launch(void* const* d_in, const int* in_sizes, int n_in,
                              void* d_out, int out_size)
{
    const float* dec = (const float*)d_in[0];
    const float* enc = (const float*)d_in[1];
    const float* Wq  = (const float*)d_in[2];
    const float* bq  = (const float*)d_in[3];
    const float* Wk  = (const float*)d_in[4];
    const float* bk  = (const float*)d_in[5];
    const float* Wv  = (const float*)d_in[6];
    const float* bv  = (const float*)d_in[7];
    const float* Wp  = (const float*)d_in[8];
    const float* bp  = (const float*)d_in[9];
    float* out = (float*)d_out;

    __nv_bfloat16 *decH,*decL,*encH,*encL;
    __nv_bfloat16 *qHp,*qLp,*kHp,*kLp,*vHp,*vLp,*yHp,*yLp;
    __nv_bfloat16 *wqH,*wqL,*wkH,*wkL,*wvH,*wvL,*wpH,*wpL;
    cudaGetSymbolAddress((void**)&decH, g_decH); cudaGetSymbolAddress((void**)&decL, g_decL);
    cudaGetSymbolAddress((void**)&encH, g_encH); cudaGetSymbolAddress((void**)&encL, g_encL);
    cudaGetSymbolAddress((void**)&qHp, g_qH);   cudaGetSymbolAddress((void**)&qLp, g_qL);
    cudaGetSymbolAddress((void**)&kHp, g_kH);   cudaGetSymbolAddress((void**)&kLp, g_kL);
    cudaGetSymbolAddress((void**)&vHp, g_vH);   cudaGetSymbolAddress((void**)&vLp, g_vL);
    cudaGetSymbolAddress((void**)&yHp, g_yH);   cudaGetSymbolAddress((void**)&yLp, g_yL);
    cudaGetSymbolAddress((void**)&wqH, g_wqH);  cudaGetSymbolAddress((void**)&wqL, g_wqL);
    cudaGetSymbolAddress((void**)&wkH, g_wkH);  cudaGetSymbolAddress((void**)&wkL, g_wkL);
    cudaGetSymbolAddress((void**)&wvH, g_wvH);  cudaGetSymbolAddress((void**)&wvL, g_wvL);
    cudaGetSymbolAddress((void**)&wpH, g_wpH);  cudaGetSymbolAddress((void**)&wpL, g_wpL);

    cudaFuncSetAttribute(gemm_hmma3, cudaFuncAttributeMaxDynamicSharedMemorySize, GSMEM);
    cudaFuncSetAttribute(attn_hmma,  cudaFuncAttributeMaxDynamicSharedMemorySize, AT_SMEM);

    split_act2<<<(2 * NACT4_ + 255) / 256, 256>>>(dec, enc, decH, decL, encH, encL);
    split_w4<<<(4 * NW4_ + 255) / 256, 256>>>(Wq, Wk, Wv, Wp,
                                              wqH, wqL, wkH, wkL,
                                              wvH, wvL, wpH, wpL);

    dim3 ggrid(D_ / 128, M_ / 128);
    gemm_hmma3<<<ggrid, 128, GSMEM>>>(decH, decL, wqH, wqL, bq,
                                      nullptr, qHp, qLp, 0.125f);
    gemm_hmma3<<<ggrid, 128, GSMEM>>>(encH, encL, wkH, wkL, bk,
                                      nullptr, kHp, kLp, 1.0f);
    gemm_hmma3<<<ggrid, 128, GSMEM>>>(encH, encL, wvH, wvL, bv,
                                      nullptr, vHp, vLp, 1.0f);

    attn_hmma<<<dim3(S_ / 128, B_ * H_), 128, AT_SMEM>>>(qHp, qLp, kHp, kLp,
                                                         vHp, vLp, yHp, yLp);

    gemm_hmma3<<<ggrid, 128, GSMEM>>>(yHp, yLp, wpH, wpL, bp,
                                      out, nullptr, nullptr, 1.0f);
}

// round 17
// speedup vs baseline: 1.0213x; 1.0213x over previous
#include <cuda_runtime.h>
#include <cuda_bf16.h>
#include <cstdint>

#define B_  2
#define S_  2048
#define D_  1024
#define H_  16
#define HD_ 64
#define M_  (B_*S_)   // 4096

// ---------------------------------------------------------------------------
// Scratch (device globals). All split bf16 pairs.
// ---------------------------------------------------------------------------
__device__ __nv_bfloat16 g_decH[M_*D_], g_decL[M_*D_];
__device__ __nv_bfloat16 g_encH[M_*D_], g_encL[M_*D_];
__device__ __nv_bfloat16 g_qH[M_*D_],   g_qL[M_*D_];
__device__ __nv_bfloat16 g_kH[M_*D_],   g_kL[M_*D_];
__device__ __nv_bfloat16 g_vH[M_*D_],   g_vL[M_*D_];
__device__ __nv_bfloat16 g_yH[M_*D_],   g_yL[M_*D_];
__device__ __nv_bfloat16 g_wqH[D_*D_],  g_wqL[D_*D_];
__device__ __nv_bfloat16 g_wkH[D_*D_],  g_wkL[D_*D_];
__device__ __nv_bfloat16 g_wvH[D_*D_],  g_wvL[D_*D_];
__device__ __nv_bfloat16 g_wpH[D_*D_],  g_wpL[D_*D_];

// ---------------------------------------------------------------------------
// fp32 -> (hi, lo) bf16 splits
// ---------------------------------------------------------------------------
__device__ __forceinline__ void split4_store(const float4 v,
                                             __nv_bfloat16* hi, __nv_bfloat16* lo, int i)
{
    float x[4] = {v.x, v.y, v.z, v.w};
    unsigned short h[4], l[4];
#pragma unroll
    for (int j = 0; j < 4; j++) {
        __nv_bfloat16 hb = __float2bfloat16(x[j]);
        __nv_bfloat16 lb = __float2bfloat16(x[j] - __bfloat162float(hb));
        h[j] = __bfloat16_as_ushort(hb);
        l[j] = __bfloat16_as_ushort(lb);
    }
    uint2 hv, lv;
    hv.x = (uint32_t)h[0] | ((uint32_t)h[1] << 16);
    hv.y = (uint32_t)h[2] | ((uint32_t)h[3] << 16);
    lv.x = (uint32_t)l[0] | ((uint32_t)l[1] << 16);
    lv.y = (uint32_t)l[2] | ((uint32_t)l[3] << 16);
    ((uint2*)hi)[i] = hv;
    ((uint2*)lo)[i] = lv;
}

#define NACT4_ (M_*D_/4)
__global__ __launch_bounds__(256)
void split_act2(const float* __restrict__ A0, const float* __restrict__ A1,
                __nv_bfloat16* __restrict__ H0, __nv_bfloat16* __restrict__ L0,
                __nv_bfloat16* __restrict__ H1, __nv_bfloat16* __restrict__ L1)
{
    int i = blockIdx.x * blockDim.x + threadIdx.x;
    int which = i >> 20;
    int idx   = i & (NACT4_ - 1);
    if (which == 0) split4_store(((const float4*)A0)[idx], H0, L0, idx);
    else            split4_store(((const float4*)A1)[idx], H1, L1, idx);
}

#define NW4_ (D_*D_/4)
__global__ __launch_bounds__(256)
void split_w2(const float* __restrict__ W0, const float* __restrict__ W1,
              __nv_bfloat16* __restrict__ H0, __nv_bfloat16* __restrict__ L0,
              __nv_bfloat16* __restrict__ H1, __nv_bfloat16* __restrict__ L1)
{
    int i = blockIdx.x * blockDim.x + threadIdx.x;
    int which = i >> 18;
    int idx   = i & (NW4_ - 1);
    if (which == 0) split4_store(((const float4*)W0)[idx], H0, L0, idx);
    else            split4_store(((const float4*)W1)[idx], H1, L1, idx);
}

// ---------------------------------------------------------------------------
// Helpers (baseline PTX only)
// ---------------------------------------------------------------------------
__device__ __forceinline__ uint32_t smem_u32(const void* p) {
    uint32_t a;
    asm("{ .reg .u64 t; cvta.to.shared.u64 t, %1; cvt.u32.u64 %0, t; }"
        : "=r"(a) : "l"(p));
    return a;
}

__device__ __forceinline__ void mma16816(float* c, const uint32_t* a, const uint32_t* b) {
    asm volatile(
        "mma.sync.aligned.m16n8k16.row.col.f32.bf16.bf16.f32 "
        "{%0,%1,%2,%3}, {%4,%5,%6,%7}, {%8,%9}, {%0,%1,%2,%3};"
        : "+f"(c[0]), "+f"(c[1]), "+f"(c[2]), "+f"(c[3])
        : "r"(a[0]), "r"(a[1]), "r"(a[2]), "r"(a[3]), "r"(b[0]), "r"(b[1]));
}

__device__ __forceinline__ void ldsm4(uint32_t& r0, uint32_t& r1,
                                      uint32_t& r2, uint32_t& r3, uint32_t addr) {
    asm volatile("ldmatrix.sync.aligned.m8n8.x4.shared.b16 {%0,%1,%2,%3}, [%4];"
                 : "=r"(r0), "=r"(r1), "=r"(r2), "=r"(r3) : "r"(addr));
}
__device__ __forceinline__ void ldsm4t(uint32_t& r0, uint32_t& r1,
                                       uint32_t& r2, uint32_t& r3, uint32_t addr) {
    asm volatile("ldmatrix.sync.aligned.m8n8.x4.trans.shared.b16 {%0,%1,%2,%3}, [%4];"
                 : "=r"(r0), "=r"(r1), "=r"(r2), "=r"(r3) : "r"(addr));
}

__device__ __forceinline__ void cp_async16(uint32_t dst, const void* src) {
    asm volatile("cp.async.cg.shared.global [%0], [%1], 16;\n"
                 :: "r"(dst), "l"(src) : "memory");
}
__device__ __forceinline__ void cp_commit() {
    asm volatile("cp.async.commit_group;\n" ::: "memory");
}
__device__ __forceinline__ void cp_wait1() {
    asm volatile("cp.async.wait_group 1;\n" ::: "memory");
}
__device__ __forceinline__ void cp_wait0() {
    asm volatile("cp.async.wait_group 0;\n" ::: "memory");
}

__device__ __forceinline__ void split2(float x, float y, uint32_t& hi, uint32_t& lo) {
    __nv_bfloat16 xh = __float2bfloat16(x);
    __nv_bfloat16 yh = __float2bfloat16(y);
    __nv_bfloat16 xl = __float2bfloat16(x - __bfloat162float(xh));
    __nv_bfloat16 yl = __float2bfloat16(y - __bfloat162float(yh));
    __nv_bfloat162 hv; hv.x = xh; hv.y = yh;
    __nv_bfloat162 lv; lv.x = xl; lv.y = yl;
    hi = *(uint32_t*)&hv; lo = *(uint32_t*)&lv;
}

// ---------------------------------------------------------------------------
// bf16x3 split GEMM body (shared by merged-QKV and output wrappers).
// CTA 128x128, 4 warps of 64x64. B resident per k-step; A streamed per mi.
// ---------------------------------------------------------------------------
#define KSTEP    32
#define NSTAGE   (D_ / KSTEP)
#define ROWH     40
#define ARRB     (128 * ROWH * 2)
#define STAGEB   (4 * ARRB)
#define GSMEM    (2 * STAGEB)

__device__ __forceinline__
void gemm_body(const __nv_bfloat16* __restrict__ Ah, const __nv_bfloat16* __restrict__ Al,
               const __nv_bfloat16* __restrict__ Wh, const __nv_bfloat16* __restrict__ Wl,
               const float* __restrict__ bias,
               float* __restrict__ CF,
               __nv_bfloat16* __restrict__ CH, __nv_bfloat16* __restrict__ CL,
               float scale, uint16_t* sm)
{
    const int tid  = threadIdx.x;
    const int wid  = tid >> 5;       // 0..3
    const int lane = tid & 31;
    const int g    = lane >> 2;
    const int t2   = (lane & 3) * 2;
    const int wm   = wid >> 1;       // 0..1
    const int wn   = wid & 1;        // 0..1
    const int bn   = blockIdx.x * 128;
    const int bm   = blockIdx.y * 128;

    const int lr   = lane & 7;
    const int lrow = lr + 8 * ((lane >> 3) & 1);   // A row sel
    const int lkh  = 8 * ((lane >> 4) & 1);        // A k sel
    const int brow = lr + 8 * ((lane >> 4) & 1);   // B row sel
    const int bk   = 8 * ((lane >> 3) & 1);        // B k sel

    const uint32_t smb = smem_u32(sm);

    auto load_stage = [&](int s) {
        const int buf = s & 1;
        const int k0  = s * KSTEP;
        const uint32_t base = smb + buf * STAGEB;
#pragma unroll
        for (int i = 0; i < 16; i++) {
            const int c   = i * 128 + tid;
            const int arr = i >> 2;              // constant per unrolled i
            const int idx = c & 511;
            const int row = idx >> 2;
            const int q   = idx & 3;
            const __nv_bfloat16* gp = (arr == 0) ? Ah : (arr == 1) ? Al
                                    : (arr == 2) ? Wh : Wl;
            const int r0 = (arr < 2) ? bm : bn;
            cp_async16(base + arr * ARRB + row * (ROWH * 2) + q * 16,
                       gp + (size_t)(r0 + row) * D_ + k0 + q * 8);
        }
        cp_commit();
    };

    float acc[4][8][4];
#pragma unroll
    for (int mi = 0; mi < 4; mi++)
#pragma unroll
        for (int nj = 0; nj < 8; nj++)
#pragma unroll
            for (int r = 0; r < 4; r++) acc[mi][nj][r] = 0.0f;

    load_stage(0);
    load_stage(1);

    for (int s = 0; s < NSTAGE; s++) {
        const int buf = s & 1;
        if (s < NSTAGE - 1) cp_wait1(); else cp_wait0();
        __syncthreads();

        const uint32_t sb = smb + buf * STAGEB;

#pragma unroll
        for (int ks = 0; ks < 2; ks++) {
            const int ko = ks * 16;

            uint32_t bh[4][4], bl[4][4];
            const uint32_t bB = sb + 2 * ARRB
                              + ((wn * 64 + brow) * ROWH + ko + bk) * 2;
#pragma unroll
            for (int jp = 0; jp < 4; jp++) {
                ldsm4(bh[jp][0], bh[jp][1], bh[jp][2], bh[jp][3],
                      bB + jp * (16 * ROWH * 2));
                ldsm4(bl[jp][0], bl[jp][1], bl[jp][2], bl[jp][3],
                      bB + ARRB + jp * (16 * ROWH * 2));
            }

            const uint32_t aA = sb + ((wm * 64 + lrow) * ROWH + ko + lkh) * 2;
#pragma unroll
            for (int mi = 0; mi < 4; mi++) {
                uint32_t ah4[4], al4[4];
                ldsm4(ah4[0], ah4[1], ah4[2], ah4[3],
                      aA + mi * (16 * ROWH * 2));
                ldsm4(al4[0], al4[1], al4[2], al4[3],
                      aA + ARRB + mi * (16 * ROWH * 2));
#pragma unroll
                for (int jp = 0; jp < 4; jp++) {
                    mma16816(acc[mi][2*jp],   ah4, &bh[jp][0]);
                    mma16816(acc[mi][2*jp+1], ah4, &bh[jp][2]);
                }
#pragma unroll
                for (int jp = 0; jp < 4; jp++) {
                    mma16816(acc[mi][2*jp],   ah4, &bl[jp][0]);
                    mma16816(acc[mi][2*jp+1], ah4, &bl[jp][2]);
                }
#pragma unroll
                for (int jp = 0; jp < 4; jp++) {
                    mma16816(acc[mi][2*jp],   al4, &bh[jp][0]);
                    mma16816(acc[mi][2*jp+1], al4, &bh[jp][2]);
                }
            }
        }
        __syncthreads();
        if (s + 2 < NSTAGE) load_stage(s + 2);
    }

    // ---- epilogue ----
#pragma unroll
    for (int mi = 0; mi < 4; mi++) {
        const int r0 = bm + wm * 64 + mi * 16 + g;
#pragma unroll
        for (int nj = 0; nj < 8; nj++) {
            const int c0 = bn + wn * 64 + nj * 8 + t2;
            const float b0 = bias[c0], b1 = bias[c0 + 1];
            float v00 = acc[mi][nj][0] + b0, v01 = acc[mi][nj][1] + b1;
            float v10 = acc[mi][nj][2] + b0, v11 = acc[mi][nj][3] + b1;
            if (CF) {
                *(float2*)&CF[(size_t)r0 * D_ + c0]       = make_float2(v00, v01);
                *(float2*)&CF[(size_t)(r0 + 8) * D_ + c0] = make_float2(v10, v11);
            } else {
                uint32_t h0, l0, h1, l1;
                split2(v00 * scale, v01 * scale, h0, l0);
                split2(v10 * scale, v11 * scale, h1, l1);
                *(uint32_t*)&CH[(size_t)r0 * D_ + c0]       = h0;
                *(uint32_t*)&CL[(size_t)r0 * D_ + c0]       = l0;
                *(uint32_t*)&CH[(size_t)(r0 + 8) * D_ + c0] = h1;
                *(uint32_t*)&CL[(size_t)(r0 + 8) * D_ + c0] = l1;
            }
        }
    }
}

// Merged Q/K/V projections: blockIdx.z selects the GEMM. 768 CTAs in one
// launch -> wave-imbalance + inter-launch drain amortized across all three.
__global__ __launch_bounds__(128, 2)
void gemm_qkv(const __nv_bfloat16* __restrict__ decH, const __nv_bfloat16* __restrict__ decL,
              const __nv_bfloat16* __restrict__ encH, const __nv_bfloat16* __restrict__ encL,
              const __nv_bfloat16* __restrict__ wqH,  const __nv_bfloat16* __restrict__ wqL,
              const __nv_bfloat16* __restrict__ wkH,  const __nv_bfloat16* __restrict__ wkL,
              const __nv_bfloat16* __restrict__ wvH,  const __nv_bfloat16* __restrict__ wvL,
              const float* __restrict__ bq, const float* __restrict__ bk,
              const float* __restrict__ bv,
              __nv_bfloat16* __restrict__ qH, __nv_bfloat16* __restrict__ qL,
              __nv_bfloat16* __restrict__ kH, __nv_bfloat16* __restrict__ kL,
              __nv_bfloat16* __restrict__ vH, __nv_bfloat16* __restrict__ vL)
{
    extern __shared__ __align__(16) uint16_t sm[];
    const int z = blockIdx.z;
    const __nv_bfloat16 *Ah, *Al, *Wh, *Wl;
    const float* bias;
    __nv_bfloat16 *CH, *CL;
    float scale;
    if (z == 0)      { Ah = decH; Al = decL; Wh = wqH; Wl = wqL; bias = bq;
                       CH = qH; CL = qL; scale = 0.125f; }
    else if (z == 1) { Ah = encH; Al = encL; Wh = wkH; Wl = wkL; bias = bk;
                       CH = kH; CL = kL; scale = 1.0f; }
    else             { Ah = encH; Al = encL; Wh = wvH; Wl = wvL; bias = bv;
                       CH = vH; CL = vL; scale = 1.0f; }
    gemm_body(Ah, Al, Wh, Wl, bias, nullptr, CH, CL, scale, sm);
}

// Output projection (fp32 store).
__global__ __launch_bounds__(128, 2)
void gemm_out(const __nv_bfloat16* __restrict__ Ah, const __nv_bfloat16* __restrict__ Al,
              const __nv_bfloat16* __restrict__ Wh, const __nv_bfloat16* __restrict__ Wl,
              const float* __restrict__ bias, float* __restrict__ CF)
{
    extern __shared__ __align__(16) uint16_t sm[];
    gemm_body(Ah, Al, Wh, Wl, bias, CF, nullptr, nullptr, 1.0f, sm);
}

// ---------------------------------------------------------------------------
// HMMA flash-attention v2 (unchanged — ~93% of measured HMMA-rate wall).
// ---------------------------------------------------------------------------
#define AT_ARR   4608
#define AT_SMEM  (8 * AT_ARR * 2)
#define NTILE_   (S_ / 64)

__global__ __launch_bounds__(128, 2)
void attn_hmma(const __nv_bfloat16* __restrict__ qH, const __nv_bfloat16* __restrict__ qL,
               const __nv_bfloat16* __restrict__ kH, const __nv_bfloat16* __restrict__ kL,
               const __nv_bfloat16* __restrict__ vH, const __nv_bfloat16* __restrict__ vL,
               __nv_bfloat16* __restrict__ yH, __nv_bfloat16* __restrict__ yL)
{
    extern __shared__ __align__(16) uint16_t sm[];
    const int tid  = threadIdx.x;
    const int wid  = tid >> 5;
    const int lane = tid & 31;
    const int g    = lane >> 2;
    const int t2   = (lane & 3) * 2;
    const int q0   = blockIdx.x * 128;
    const int bh   = blockIdx.y;
    const int b    = bh >> 4;
    const int h    = bh & 15;
    const int col0 = h * HD_;
    const int m0   = b * S_ + q0 + wid * 32;

    const int krow = (lane & 7) + 8 * ((lane >> 4) & 1);
    const int kc16 = 16 * ((lane >> 3) & 1);
    const int vrow = (lane & 7) + 8 * ((lane >> 3) & 1);
    const int vc16 = 16 * ((lane >> 4) & 1);

    uint32_t qh[2][4][4], ql[2][4][4];
#pragma unroll
    for (int mi = 0; mi < 2; mi++) {
        const int r0 = m0 + mi * 16;
        const __nv_bfloat16* p0h = qH + (size_t)(r0 + g) * D_ + col0;
        const __nv_bfloat16* p1h = qH + (size_t)(r0 + g + 8) * D_ + col0;
        const __nv_bfloat16* p0l = qL + (size_t)(r0 + g) * D_ + col0;
        const __nv_bfloat16* p1l = qL + (size_t)(r0 + g + 8) * D_ + col0;
#pragma unroll
        for (int kc = 0; kc < 4; kc++) {
            qh[mi][kc][0] = *(const uint32_t*)(p0h + kc * 16 + t2);
            qh[mi][kc][1] = *(const uint32_t*)(p1h + kc * 16 + t2);
            qh[mi][kc][2] = *(const uint32_t*)(p0h + kc * 16 + t2 + 8);
            qh[mi][kc][3] = *(const uint32_t*)(p1h + kc * 16 + t2 + 8);
            ql[mi][kc][0] = *(const uint32_t*)(p0l + kc * 16 + t2);
            ql[mi][kc][1] = *(const uint32_t*)(p1l + kc * 16 + t2);
            ql[mi][kc][2] = *(const uint32_t*)(p0l + kc * 16 + t2 + 8);
            ql[mi][kc][3] = *(const uint32_t*)(p1l + kc * 16 + t2 + 8);
        }
    }

    const uint32_t smb = smem_u32(sm);
    const __nv_bfloat16* gsrc[4] = {kH, kL, vH, vL};

    auto load_tile = [&](int kb, int buf) {
#pragma unroll
        for (int i = 0; i < 16; i++) {
            int c = i * 128 + tid;
            int a = c >> 9;
            int idx = c & 511;
            int row = idx >> 3, qq = idx & 7;
            uint32_t dst = smb + ((buf * 4 + a) * AT_ARR + row * 72 + qq * 8) * 2;
            const __nv_bfloat16* src = gsrc[a]
                + (size_t)(b * S_ + kb + row) * D_ + col0 + qq * 8;
            cp_async16(dst, src);
        }
        cp_commit();
    };

    float of[2][8][4];
#pragma unroll
    for (int mi = 0; mi < 2; mi++)
#pragma unroll
        for (int j = 0; j < 8; j++)
#pragma unroll
            for (int r = 0; r < 4; r++) of[mi][j][r] = 0.0f;
    float mr[4] = {-1e30f, -1e30f, -1e30f, -1e30f};
    float lr[4] = {0.0f, 0.0f, 0.0f, 0.0f};

    load_tile(0, 0);

    for (int it = 0; it < NTILE_; it++) {
        const int buf = it & 1;
        cp_wait0();
        __syncthreads();
        if (it + 1 < NTILE_) load_tile((it + 1) * 64, buf ^ 1);

        const uint32_t Khb = smb + (buf * 4 + 0) * AT_ARR * 2;
        const uint32_t Klb = smb + (buf * 4 + 1) * AT_ARR * 2;
        const uint32_t Vhb = smb + (buf * 4 + 2) * AT_ARR * 2;
        const uint32_t Vlb = smb + (buf * 4 + 3) * AT_ARR * 2;

        float sf[2][8][4];
#pragma unroll
        for (int mi = 0; mi < 2; mi++)
#pragma unroll
            for (int j = 0; j < 8; j++)
#pragma unroll
                for (int r = 0; r < 4; r++) sf[mi][j][r] = 0.0f;

#pragma unroll
        for (int kc = 0; kc < 4; kc++) {
#pragma unroll
            for (int jp = 0; jp < 4; jp++) {
                uint32_t kh4[4], kl4[4];
                const uint32_t off = (jp * 16 + krow) * 144 + kc * 32 + kc16;
                ldsm4(kh4[0], kh4[1], kh4[2], kh4[3], Khb + off);
                ldsm4(kl4[0], kl4[1], kl4[2], kl4[3], Klb + off);
#pragma unroll
                for (int mi = 0; mi < 2; mi++) {
                    mma16816(sf[mi][2*jp],   qh[mi][kc], &kh4[0]);
                    mma16816(sf[mi][2*jp+1], qh[mi][kc], &kh4[2]);
                }
#pragma unroll
                for (int mi = 0; mi < 2; mi++) {
                    mma16816(sf[mi][2*jp],   qh[mi][kc], &kl4[0]);
                    mma16816(sf[mi][2*jp+1], qh[mi][kc], &kl4[2]);
                }
#pragma unroll
                for (int mi = 0; mi < 2; mi++) {
                    mma16816(sf[mi][2*jp],   ql[mi][kc], &kh4[0]);
                    mma16816(sf[mi][2*jp+1], ql[mi][kc], &kh4[2]);
                }
            }
        }

#pragma unroll
        for (int mi = 0; mi < 2; mi++) {
            float tm0 = -1e30f, tm1 = -1e30f;
#pragma unroll
            for (int j = 0; j < 8; j++) {
                tm0 = fmaxf(tm0, fmaxf(sf[mi][j][0], sf[mi][j][1]));
                tm1 = fmaxf(tm1, fmaxf(sf[mi][j][2], sf[mi][j][3]));
            }
            tm0 = fmaxf(tm0, __shfl_xor_sync(0xffffffffu, tm0, 1));
            tm0 = fmaxf(tm0, __shfl_xor_sync(0xffffffffu, tm0, 2));
            tm1 = fmaxf(tm1, __shfl_xor_sync(0xffffffffu, tm1, 1));
            tm1 = fmaxf(tm1, __shfl_xor_sync(0xffffffffu, tm1, 2));
            const float mn0 = fmaxf(mr[mi*2],   tm0);
            const float mn1 = fmaxf(mr[mi*2+1], tm1);
            const float al0 = __expf(mr[mi*2]   - mn0);
            const float al1 = __expf(mr[mi*2+1] - mn1);
            float rs0 = 0.0f, rs1 = 0.0f;
#pragma unroll
            for (int j = 0; j < 8; j++) {
                sf[mi][j][0] = __expf(sf[mi][j][0] - mn0);
                sf[mi][j][1] = __expf(sf[mi][j][1] - mn0);
                sf[mi][j][2] = __expf(sf[mi][j][2] - mn1);
                sf[mi][j][3] = __expf(sf[mi][j][3] - mn1);
                rs0 += sf[mi][j][0] + sf[mi][j][1];
                rs1 += sf[mi][j][2] + sf[mi][j][3];
            }
            rs0 += __shfl_xor_sync(0xffffffffu, rs0, 1);
            rs0 += __shfl_xor_sync(0xffffffffu, rs0, 2);
            rs1 += __shfl_xor_sync(0xffffffffu, rs1, 1);
            rs1 += __shfl_xor_sync(0xffffffffu, rs1, 2);
            lr[mi*2]   = lr[mi*2]   * al0 + rs0;
            lr[mi*2+1] = lr[mi*2+1] * al1 + rs1;
            mr[mi*2] = mn0; mr[mi*2+1] = mn1;
#pragma unroll
            for (int j = 0; j < 8; j++) {
                of[mi][j][0] *= al0; of[mi][j][1] *= al0;
                of[mi][j][2] *= al1; of[mi][j][3] *= al1;
            }
        }

#pragma unroll
        for (int kc = 0; kc < 4; kc++) {
            uint32_t pah[2][4], pal[2][4];
#pragma unroll
            for (int mi = 0; mi < 2; mi++) {
                split2(sf[mi][2*kc][0],   sf[mi][2*kc][1],   pah[mi][0], pal[mi][0]);
                split2(sf[mi][2*kc][2],   sf[mi][2*kc][3],   pah[mi][1], pal[mi][1]);
                split2(sf[mi][2*kc+1][0], sf[mi][2*kc+1][1], pah[mi][2], pal[mi][2]);
                split2(sf[mi][2*kc+1][2], sf[mi][2*kc+1][3], pah[mi][3], pal[mi][3]);
            }
#pragma unroll
            for (int dp = 0; dp < 4; dp++) {
                uint32_t vh4[4], vl4[4];
                const uint32_t off = (kc * 16 + vrow) * 144 + dp * 32 + vc16;
                ldsm4t(vh4[0], vh4[1], vh4[2], vh4[3], Vhb + off);
                ldsm4t(vl4[0], vl4[1], vl4[2], vl4[3], Vlb + off);
#pragma unroll
                for (int mi = 0; mi < 2; mi++) {
                    mma16816(of[mi][2*dp],   pah[mi], &vh4[0]);
                    mma16816(of[mi][2*dp+1], pah[mi], &vh4[2]);
                }
#pragma unroll
                for (int mi = 0; mi < 2; mi++) {
                    mma16816(of[mi][2*dp],   pah[mi], &vl4[0]);
                    mma16816(of[mi][2*dp+1], pah[mi], &vl4[2]);
                }
#pragma unroll
                for (int mi = 0; mi < 2; mi++) {
                    mma16816(of[mi][2*dp],   pal[mi], &vh4[0]);
                    mma16816(of[mi][2*dp+1], pal[mi], &vh4[2]);
                }
            }
        }
    }

#pragma unroll
    for (int mi = 0; mi < 2; mi++) {
        const float inv0 = 1.0f / lr[mi*2];
        const float inv1 = 1.0f / lr[mi*2+1];
        const int r0 = m0 + mi * 16;
#pragma unroll
        for (int j = 0; j < 8; j++) {
            uint32_t h0, l0, h1, l1;
            split2(of[mi][j][0] * inv0, of[mi][j][1] * inv0, h0, l0);
            split2(of[mi][j][2] * inv1, of[mi][j][3] * inv1, h1, l1);
            const size_t o0 = (size_t)(r0 + g) * D_ + col0 + j * 8 + t2;
            const size_t o1 = (size_t)(r0 + g + 8) * D_ + col0 + j * 8 + t2;
            *(uint32_t*)&yH[o0] = h0;
            *(uint32_t*)&yL[o0] = l0;
            *(uint32_t*)&yH[o1] = h1;
            *(uint32_t*)&yL[o1] = l1;
        }
    }
}

// ---------------------------------------------------------------------------
// Launch. 6 launches/iter -> ncu -s 5 -c 1 captures gemm_out.
// ---------------------------------------------------------------------------
extern "C" void kernel_launch(void* const* d_in, const int* in_sizes, int n_in,
                              void* d_out, int out_size)
{
    const float* dec = (const float*)d_in[0];
    const float* enc = (const float*)d_in[1];
    const float* Wq  = (const float*)d_in[2];
    const float* bq  = (const float*)d_in[3];
    const float* Wk  = (const float*)d_in[4];
    const float* bk  = (const float*)d_in[5];
    const float* Wv  = (const float*)d_in[6];
    const float* bv  = (const float*)d_in[7];
    const float* Wp  = (const float*)d_in[8];
    const float* bp  = (const float*)d_in[9];
    float* out = (float*)d_out;

    __nv_bfloat16 *decH,*decL,*encH,*encL;
    __nv_bfloat16 *qHp,*qLp,*kHp,*kLp,*vHp,*vLp,*yHp,*yLp;
    __nv_bfloat16 *wqH,*wqL,*wkH,*wkL,*wvH,*wvL,*wpH,*wpL;
    cudaGetSymbolAddress((void**)&decH, g_decH); cudaGetSymbolAddress((void**)&decL, g_decL);
    cudaGetSymbolAddress((void**)&encH, g_encH); cudaGetSymbolAddress((void**)&encL, g_encL);
    cudaGetSymbolAddress((void**)&qHp, g_qH);   cudaGetSymbolAddress((void**)&qLp, g_qL);
    cudaGetSymbolAddress((void**)&kHp, g_kH);   cudaGetSymbolAddress((void**)&kLp, g_kL);
    cudaGetSymbolAddress((void**)&vHp, g_vH);   cudaGetSymbolAddress((void**)&vLp, g_vL);
    cudaGetSymbolAddress((void**)&yHp, g_yH);   cudaGetSymbolAddress((void**)&yLp, g_yL);
    cudaGetSymbolAddress((void**)&wqH, g_wqH);  cudaGetSymbolAddress((void**)&wqL, g_wqL);
    cudaGetSymbolAddress((void**)&wkH, g_wkH);  cudaGetSymbolAddress((void**)&wkL, g_wkL);
    cudaGetSymbolAddress((void**)&wvH, g_wvH);  cudaGetSymbolAddress((void**)&wvL, g_wvL);
    cudaGetSymbolAddress((void**)&wpH, g_wpH);  cudaGetSymbolAddress((void**)&wpL, g_wpL);

    cudaFuncSetAttribute(gemm_qkv, cudaFuncAttributeMaxDynamicSharedMemorySize, GSMEM);
    cudaFuncSetAttribute(gemm_out, cudaFuncAttributeMaxDynamicSharedMemorySize, GSMEM);
    cudaFuncSetAttribute(attn_hmma, cudaFuncAttributeMaxDynamicSharedMemorySize, AT_SMEM);

    // 1: activation splits; 2,3: weight splits
    split_act2<<<(2 * NACT4_ + 255) / 256, 256>>>(dec, enc, decH, decL, encH, encL);
    split_w2<<<(2 * NW4_ + 255) / 256, 256>>>(Wq, Wk, wqH, wqL, wkH, wkL);
    split_w2<<<(2 * NW4_ + 255) / 256, 256>>>(Wv, Wp, wvH, wvL, wpH, wpL);

    // 4: merged Q/K/V projections (768 CTAs, one launch)
    gemm_qkv<<<dim3(D_ / 128, M_ / 128, 3), 128, GSMEM>>>(
        decH, decL, encH, encL,
        wqH, wqL, wkH, wkL, wvH, wvL,
        bq, bk, bv,
        qHp, qLp, kHp, kLp, vHp, vLp);

    // 5: attention
    attn_hmma<<<dim3(S_ / 128, B_ * H_), 128, AT_SMEM>>>(qHp, qLp, kHp, kLp,
                                                         vHp, vLp, yHp, yLp);

    // 6: output projection (ncu capture target)
    gemm_out<<<dim3(D_ / 128, M_ / 128), 128, GSMEM>>>(yHp, yLp, wpH, wpL, bp, out);
}